// round 2
// baseline (speedup 1.0000x reference)
#include <cuda_runtime.h>
#include <math.h>

#define B_  4
#define S_  2048
#define D_  2048
#define H_  16
#define DH_ 128
#define M_  (B_*S_)

// 64 MB each of scratch (allowed: __device__ globals, no runtime allocation)
__device__ float g_q[(size_t)B_*H_*S_*DH_];
__device__ float g_k[(size_t)B_*H_*S_*DH_];
__device__ float g_v[(size_t)B_*H_*S_*DH_];
__device__ float g_ctx[(size_t)B_*S_*D_];

// ---------------------------------------------------------------------------
// GEMM: C[m][n] = sum_k A[m][k] * W[n][k] + bias[n]
// A: [M, K] row-major, W: [N, K] row-major (NT layout — both K-contiguous)
// 128x128 block tile, TK=16, 256 threads, 8x8 microtile per thread.
// HEADS=true scatters output into [B, H, S, Dh]; else [M, N] row-major.
// ---------------------------------------------------------------------------
template<bool HEADS>
__global__ __launch_bounds__(256)
void gemm128(const float* __restrict__ A, const float* __restrict__ W,
             const float* __restrict__ bias, float* __restrict__ C)
{
    __shared__ float As[16][128];
    __shared__ float Ws[16][128];
    const int K = D_;
    const int m0 = blockIdx.y * 128;
    const int n0 = blockIdx.x * 128;
    const int tid = threadIdx.x;
    const int tx = tid & 15;      // col group
    const int ty = tid >> 4;      // row group

    float acc[8][8];
#pragma unroll
    for (int i = 0; i < 8; i++)
#pragma unroll
        for (int j = 0; j < 8; j++) acc[i][j] = 0.f;

    for (int k0 = 0; k0 < K; k0 += 16) {
        // Load 128x16 A-tile and W-tile (512 float4 each), store transposed.
#pragma unroll
        for (int i = tid; i < 512; i += 256) {
            const int r = i >> 2, c4 = i & 3;
            float4 av = *(const float4*)(A + (size_t)(m0 + r) * K + k0 + c4 * 4);
            As[c4*4+0][r] = av.x; As[c4*4+1][r] = av.y;
            As[c4*4+2][r] = av.z; As[c4*4+3][r] = av.w;
            float4 wv = *(const float4*)(W + (size_t)(n0 + r) * K + k0 + c4 * 4);
            Ws[c4*4+0][r] = wv.x; Ws[c4*4+1][r] = wv.y;
            Ws[c4*4+2][r] = wv.z; Ws[c4*4+3][r] = wv.w;
        }
        __syncthreads();
#pragma unroll
        for (int k = 0; k < 16; k++) {
            float a[8], b[8];
            *(float4*)(a)     = *(const float4*)(&As[k][ty*8]);
            *(float4*)(a + 4) = *(const float4*)(&As[k][ty*8 + 4]);
            *(float4*)(b)     = *(const float4*)(&Ws[k][tx*8]);
            *(float4*)(b + 4) = *(const float4*)(&Ws[k][tx*8 + 4]);
#pragma unroll
            for (int i = 0; i < 8; i++)
#pragma unroll
                for (int j = 0; j < 8; j++)
                    acc[i][j] += a[i] * b[j];
        }
        __syncthreads();
    }

#pragma unroll
    for (int i = 0; i < 8; i++) {
        const int m = m0 + ty * 8 + i;
#pragma unroll
        for (int j = 0; j < 8; j++) {
            const int n = n0 + tx * 8 + j;
            const float v = acc[i][j] + bias[n];
            if (HEADS) {
                const int bb = m >> 11, s = m & (S_ - 1);
                const int h = n >> 7, dh = n & 127;
                C[(((size_t)bb * H_ + h) * S_ + s) * DH_ + dh] = v;
            } else {
                C[(size_t)m * D_ + n] = v;
            }
        }
    }
}

// ---------------------------------------------------------------------------
// RoPE in-place on [B,H,S,Dh] tensor. One thread per (row, pair).
// ---------------------------------------------------------------------------
__global__ __launch_bounds__(256)
void rope_kernel(float* __restrict__ t)
{
    const int idx = blockIdx.x * blockDim.x + threadIdx.x;  // B*H*S*64 threads
    const int p   = idx & 63;
    const int row = idx >> 6;                               // b*H*S + h*S + s
    const int s   = row & (S_ - 1);

    // inv_freq computed in double then rounded to fp32 (tracks jax fp32 value)
    const float invf = (float)exp(-(double)p * (log(10000.0) / 64.0));
    const float ang  = (float)s * invf;
    float sn, cs;
    sincosf(ang, &sn, &cs);

    float* base = t + (size_t)row * DH_;
    const float v1 = base[p];
    const float v2 = base[p + 64];
    base[p]      = v1 * cs - v2 * sn;
    base[p + 64] = v2 * cs + v1 * sn;
}

// ---------------------------------------------------------------------------
// Flash attention, fp32, non-causal.
// Grid: (S/64, B*H). Block: 128 threads.
// Thread t: g = t&3, r = t>>2. Owns q-rows r and r+32, dims d = 16*jj + 4*g + e.
// Per KV tile (64 keys): compute scores (shfl-reduced 4-way dots, stored
// transposed in Ss[c][r]), online-softmax rescale, then P·V from the same
// smem buffer reloaded with V. All smem accesses are conflict-free LDS.128.
// ---------------------------------------------------------------------------
__global__ __launch_bounds__(128)
void attn_kernel(float* __restrict__ ctx)
{
    __shared__ float KV[64][128];   // 32 KB, holds K then V per tile
    __shared__ float Ss[64][64];    // 16 KB, scores transposed [c][r]

    const int bh  = blockIdx.y;         // b*H + h
    const int m0  = blockIdx.x * 64;
    const int tid = threadIdx.x;
    const int g   = tid & 3;
    const int r   = tid >> 2;           // 0..31

    const float* Qb = g_q + (size_t)bh * S_ * DH_;
    const float* Kb = g_k + (size_t)bh * S_ * DH_;
    const float* Vb = g_v + (size_t)bh * S_ * DH_;

    float q0[32], q1[32], a0[32], a1[32];
#pragma unroll
    for (int jj = 0; jj < 8; jj++) {
        *(float4*)(&q0[jj*4]) = *(const float4*)(Qb + (size_t)(m0 + r)      * DH_ + jj*16 + g*4);
        *(float4*)(&q1[jj*4]) = *(const float4*)(Qb + (size_t)(m0 + r + 32) * DH_ + jj*16 + g*4);
    }
#pragma unroll
    for (int j = 0; j < 32; j++) { a0[j] = 0.f; a1[j] = 0.f; }

    float mo0 = -1e30f, mo1 = -1e30f, l0 = 0.f, l1 = 0.f;
    const float scale = 0.08838834764831845f;   // 1/sqrt(128)

    for (int n0 = 0; n0 < S_; n0 += 64) {
        // ---- load K tile ----
        __syncthreads();
#pragma unroll
        for (int i = tid; i < 2048; i += 128) {
            const int rr = i >> 5, c = i & 31;
            *(float4*)(&KV[rr][c*4]) = *(const float4*)(Kb + (size_t)(n0 + rr) * DH_ + c*4);
        }
        __syncthreads();

        // ---- scores ----
        float mt0 = mo0, mt1 = mo1;
#pragma unroll 2
        for (int c = 0; c < 64; c++) {
            float p0 = 0.f, p1 = 0.f;
#pragma unroll
            for (int jj = 0; jj < 8; jj++) {
                const float4 kv = *(const float4*)(&KV[c][jj*16 + g*4]);
                p0 += q0[jj*4+0]*kv.x + q0[jj*4+1]*kv.y + q0[jj*4+2]*kv.z + q0[jj*4+3]*kv.w;
                p1 += q1[jj*4+0]*kv.x + q1[jj*4+1]*kv.y + q1[jj*4+2]*kv.z + q1[jj*4+3]*kv.w;
            }
            p0 += __shfl_xor_sync(0xffffffffu, p0, 1);
            p0 += __shfl_xor_sync(0xffffffffu, p0, 2);
            p1 += __shfl_xor_sync(0xffffffffu, p1, 1);
            p1 += __shfl_xor_sync(0xffffffffu, p1, 2);
            p0 *= scale; p1 *= scale;
            mt0 = fmaxf(mt0, p0); mt1 = fmaxf(mt1, p1);
            if (g == 0) { Ss[c][r] = p0; Ss[c][r + 32] = p1; }
        }

        // ---- online softmax rescale ----
        const float c0 = __expf(mo0 - mt0);
        const float c1 = __expf(mo1 - mt1);
        l0 *= c0; l1 *= c1;
#pragma unroll
        for (int j = 0; j < 32; j++) { a0[j] *= c0; a1[j] *= c1; }
        mo0 = mt0; mo1 = mt1;

        // ---- load V tile (reuse buffer) ----
        __syncthreads();
#pragma unroll
        for (int i = tid; i < 2048; i += 128) {
            const int rr = i >> 5, c = i & 31;
            *(float4*)(&KV[rr][c*4]) = *(const float4*)(Vb + (size_t)(n0 + rr) * DH_ + c*4);
        }
        __syncthreads();

        // ---- P . V ----
#pragma unroll 2
        for (int c = 0; c < 64; c++) {
            const float p0 = __expf(Ss[c][r]      - mo0);
            const float p1 = __expf(Ss[c][r + 32] - mo1);
            l0 += p0; l1 += p1;
#pragma unroll
            for (int jj = 0; jj < 8; jj++) {
                const float4 v = *(const float4*)(&KV[c][jj*16 + g*4]);
                a0[jj*4+0] += p0*v.x; a0[jj*4+1] += p0*v.y;
                a0[jj*4+2] += p0*v.z; a0[jj*4+3] += p0*v.w;
                a1[jj*4+0] += p1*v.x; a1[jj*4+1] += p1*v.y;
                a1[jj*4+2] += p1*v.z; a1[jj*4+3] += p1*v.w;
            }
        }
    }

    const float i0 = 1.f / l0, i1 = 1.f / l1;
    const int bb = bh >> 4, h = bh & 15;
    float* o0 = ctx + ((size_t)bb * S_ + m0 + r)      * D_ + h * DH_;
    float* o1 = ctx + ((size_t)bb * S_ + m0 + r + 32) * D_ + h * DH_;
#pragma unroll
    for (int jj = 0; jj < 8; jj++) {
        float4 w0 = make_float4(a0[jj*4]*i0, a0[jj*4+1]*i0, a0[jj*4+2]*i0, a0[jj*4+3]*i0);
        float4 w1 = make_float4(a1[jj*4]*i1, a1[jj*4+1]*i1, a1[jj*4+2]*i1, a1[jj*4+3]*i1);
        *(float4*)(&o0[jj*16 + g*4]) = w0;
        *(float4*)(&o1[jj*16 + g*4]) = w1;
    }
}

// ---------------------------------------------------------------------------
extern "C" void kernel_launch(void* const* d_in, const int* in_sizes, int n_in,
                              void* d_out, int out_size)
{
    const float* x  = (const float*)d_in[0];
    const float* wq = (const float*)d_in[1];
    const float* bq = (const float*)d_in[2];
    const float* wk = (const float*)d_in[3];
    const float* bk = (const float*)d_in[4];
    const float* wv = (const float*)d_in[5];
    const float* bv = (const float*)d_in[6];
    const float* wo = (const float*)d_in[7];
    const float* bo = (const float*)d_in[8];
    float* out = (float*)d_out;

    float *q, *k, *v, *ctx;
    cudaGetSymbolAddress((void**)&q,   g_q);
    cudaGetSymbolAddress((void**)&k,   g_k);
    cudaGetSymbolAddress((void**)&v,   g_v);
    cudaGetSymbolAddress((void**)&ctx, g_ctx);

    const dim3 ggrid(D_ / 128, M_ / 128);   // (16, 64)

    gemm128<true><<<ggrid, 256>>>(x, wq, bq, q);
    gemm128<true><<<ggrid, 256>>>(x, wk, bk, k);
    gemm128<true><<<ggrid, 256>>>(x, wv, bv, v);

    const int rope_threads = B_ * H_ * S_ * 64;     // one per rotation pair
    rope_kernel<<<rope_threads / 256, 256>>>(q);
    rope_kernel<<<rope_threads / 256, 256>>>(k);

    attn_kernel<<<dim3(S_ / 64, B_ * H_), 128>>>(ctx);

    gemm128<false><<<ggrid, 256>>>(ctx, wo, bo, out);
}

// round 3
// speedup vs baseline: 1.8168x; 1.8168x over previous
#include <cuda_runtime.h>
#include <math.h>
#include <stdint.h>

#define B_  4
#define S_  2048
#define D_  2048
#define H_  16
#define DH_ 128
#define M_  (B_*S_)

// Scratch (allowed: __device__ globals)
__device__ float g_q[(size_t)B_*H_*S_*DH_];
__device__ float g_k[(size_t)B_*H_*S_*DH_];
__device__ float g_v[(size_t)B_*H_*S_*DH_];
__device__ float g_ctx[(size_t)B_*S_*D_];
__device__ float g_cos[(size_t)S_*64];
__device__ float g_sin[(size_t)S_*64];

// ---------------------------------------------------------------------------
// TF32 helpers
// ---------------------------------------------------------------------------
__device__ __forceinline__ float f2tf32(float x) {
    uint32_t r;
    asm("cvt.rna.tf32.f32 %0, %1;" : "=r"(r) : "f"(x));
    return __uint_as_float(r);
}

__device__ __forceinline__ void mma_tf32(float c[4], const uint32_t a[4], const uint32_t b[2]) {
    asm volatile(
        "mma.sync.aligned.m16n8k8.row.col.f32.tf32.tf32.f32 "
        "{%0,%1,%2,%3}, {%4,%5,%6,%7}, {%8,%9}, {%0,%1,%2,%3};"
        : "+f"(c[0]), "+f"(c[1]), "+f"(c[2]), "+f"(c[3])
        : "r"(a[0]), "r"(a[1]), "r"(a[2]), "r"(a[3]), "r"(b[0]), "r"(b[1]));
}

// ---------------------------------------------------------------------------
// TF32 tensor-core GEMM: C[m][n] = sum_k A[m][k]*W[n][k] + bias[n]
// 128x128 tile, BK=16, 256 threads (2x4 warps), 64x32 warp tile.
// Smem row stride 20 floats -> all fragment loads conflict-free.
// HEADS=true scatters into [B,H,S,Dh].
// ---------------------------------------------------------------------------
template<bool HEADS>
__global__ __launch_bounds__(256)
void gemm_tf32(const float* __restrict__ A, const float* __restrict__ W,
               const float* __restrict__ bias, float* __restrict__ C)
{
    __shared__ float As[128][20];
    __shared__ float Ws[128][20];
    const int K  = D_;
    const int m0 = blockIdx.y * 128;
    const int n0 = blockIdx.x * 128;
    const int tid  = threadIdx.x;
    const int warp = tid >> 5, lane = tid & 31;
    const int wy = warp >> 2, wx = warp & 3;   // 2x4 warp grid

    float acc[4][4][4];
#pragma unroll
    for (int ti = 0; ti < 4; ti++)
#pragma unroll
        for (int tj = 0; tj < 4; tj++)
#pragma unroll
            for (int e = 0; e < 4; e++) acc[ti][tj][e] = 0.f;

    const int lr = lane >> 2;     // 0..7
    const int lc = lane & 3;      // 0..3

    for (int k0 = 0; k0 < K; k0 += 16) {
        // load 128x16 A and W tiles, convert to tf32 at store
#pragma unroll
        for (int u = 0; u < 2; u++) {
            const int f  = tid + u * 256;       // float4 index 0..511
            const int r  = f >> 2, c4 = f & 3;
            float4 av = *(const float4*)(A + (size_t)(m0 + r) * K + k0 + c4 * 4);
            av.x = f2tf32(av.x); av.y = f2tf32(av.y);
            av.z = f2tf32(av.z); av.w = f2tf32(av.w);
            *(float4*)(&As[r][c4 * 4]) = av;
            float4 wv = *(const float4*)(W + (size_t)(n0 + r) * K + k0 + c4 * 4);
            wv.x = f2tf32(wv.x); wv.y = f2tf32(wv.y);
            wv.z = f2tf32(wv.z); wv.w = f2tf32(wv.w);
            *(float4*)(&Ws[r][c4 * 4]) = wv;
        }
        __syncthreads();

#pragma unroll
        for (int kk = 0; kk < 16; kk += 8) {
            uint32_t afr[4][4], bfr[4][2];
            const int ac = kk + lc;
#pragma unroll
            for (int ti = 0; ti < 4; ti++) {
                const int ar = wy * 64 + ti * 16 + lr;
                afr[ti][0] = __float_as_uint(As[ar    ][ac]);
                afr[ti][1] = __float_as_uint(As[ar + 8][ac]);
                afr[ti][2] = __float_as_uint(As[ar    ][ac + 4]);
                afr[ti][3] = __float_as_uint(As[ar + 8][ac + 4]);
            }
#pragma unroll
            for (int tj = 0; tj < 4; tj++) {
                const int br = wx * 32 + tj * 8 + lr;
                bfr[tj][0] = __float_as_uint(Ws[br][ac]);
                bfr[tj][1] = __float_as_uint(Ws[br][ac + 4]);
            }
#pragma unroll
            for (int ti = 0; ti < 4; ti++)
#pragma unroll
                for (int tj = 0; tj < 4; tj++)
                    mma_tf32(acc[ti][tj], afr[ti], bfr[tj]);
        }
        __syncthreads();
    }

    // epilogue: c0:(r,c) c1:(r,c+1) c2:(r+8,c) c3:(r+8,c+1), c=(lane%4)*2
#pragma unroll
    for (int ti = 0; ti < 4; ti++) {
#pragma unroll
        for (int tj = 0; tj < 4; tj++) {
            const int row = m0 + wy * 64 + ti * 16 + lr;
            const int col = n0 + wx * 32 + tj * 8 + lc * 2;
#pragma unroll
            for (int e = 0; e < 4; e++) {
                const int m = row + (e >> 1) * 8;
                const int n = col + (e & 1);
                const float v = acc[ti][tj][e] + bias[n];
                if (HEADS) {
                    const int bb = m >> 11, s = m & (S_ - 1);
                    const int h = n >> 7, dh = n & 127;
                    C[(((size_t)bb * H_ + h) * S_ + s) * DH_ + dh] = v;
                } else {
                    C[(size_t)m * D_ + n] = v;
                }
            }
        }
    }
}

// ---------------------------------------------------------------------------
// RoPE: precompute cos/sin table once (fp64 transcendentals on the fp32
// reference angle), then a pure streaming apply kernel.
// ---------------------------------------------------------------------------
__global__ __launch_bounds__(256)
void rope_table_kernel()
{
    const int idx = blockIdx.x * blockDim.x + threadIdx.x;  // S_*64
    const int p = idx & 63;
    const int s = idx >> 6;
    // match jax fp32 pipeline: invf and angle rounded to fp32, then exact cos/sin
    const float invf = (float)exp(-(double)p * (log(10000.0) / 64.0));
    const float ang  = (float)s * invf;
    g_cos[idx] = (float)cos((double)ang);
    g_sin[idx] = (float)sin((double)ang);
}

__global__ __launch_bounds__(256)
void rope_apply_kernel(float* __restrict__ t)
{
    const int idx = blockIdx.x * blockDim.x + threadIdx.x;  // B*H*S*64
    const int p   = idx & 63;
    const int row = idx >> 6;
    const int s   = row & (S_ - 1);

    const float cs = g_cos[s * 64 + p];
    const float sn = g_sin[s * 64 + p];

    float* base = t + (size_t)row * DH_;
    const float v1 = base[p];
    const float v2 = base[p + 64];
    base[p]      = v1 * cs - v2 * sn;
    base[p + 64] = v2 * cs + v1 * sn;
}

// ---------------------------------------------------------------------------
// Flash attention, fp32, non-causal (unchanged from R1 baseline).
// ---------------------------------------------------------------------------
__global__ __launch_bounds__(128)
void attn_kernel(float* __restrict__ ctx)
{
    __shared__ float KV[64][128];
    __shared__ float Ss[64][64];

    const int bh  = blockIdx.y;
    const int m0  = blockIdx.x * 64;
    const int tid = threadIdx.x;
    const int g   = tid & 3;
    const int r   = tid >> 2;

    const float* Qb = g_q + (size_t)bh * S_ * DH_;
    const float* Kb = g_k + (size_t)bh * S_ * DH_;
    const float* Vb = g_v + (size_t)bh * S_ * DH_;

    float q0[32], q1[32], a0[32], a1[32];
#pragma unroll
    for (int jj = 0; jj < 8; jj++) {
        *(float4*)(&q0[jj*4]) = *(const float4*)(Qb + (size_t)(m0 + r)      * DH_ + jj*16 + g*4);
        *(float4*)(&q1[jj*4]) = *(const float4*)(Qb + (size_t)(m0 + r + 32) * DH_ + jj*16 + g*4);
    }
#pragma unroll
    for (int j = 0; j < 32; j++) { a0[j] = 0.f; a1[j] = 0.f; }

    float mo0 = -1e30f, mo1 = -1e30f, l0 = 0.f, l1 = 0.f;
    const float scale = 0.08838834764831845f;

    for (int n0 = 0; n0 < S_; n0 += 64) {
        __syncthreads();
#pragma unroll
        for (int i = tid; i < 2048; i += 128) {
            const int rr = i >> 5, c = i & 31;
            *(float4*)(&KV[rr][c*4]) = *(const float4*)(Kb + (size_t)(n0 + rr) * DH_ + c*4);
        }
        __syncthreads();

        float mt0 = mo0, mt1 = mo1;
#pragma unroll 2
        for (int c = 0; c < 64; c++) {
            float p0 = 0.f, p1 = 0.f;
#pragma unroll
            for (int jj = 0; jj < 8; jj++) {
                const float4 kv = *(const float4*)(&KV[c][jj*16 + g*4]);
                p0 += q0[jj*4+0]*kv.x + q0[jj*4+1]*kv.y + q0[jj*4+2]*kv.z + q0[jj*4+3]*kv.w;
                p1 += q1[jj*4+0]*kv.x + q1[jj*4+1]*kv.y + q1[jj*4+2]*kv.z + q1[jj*4+3]*kv.w;
            }
            p0 += __shfl_xor_sync(0xffffffffu, p0, 1);
            p0 += __shfl_xor_sync(0xffffffffu, p0, 2);
            p1 += __shfl_xor_sync(0xffffffffu, p1, 1);
            p1 += __shfl_xor_sync(0xffffffffu, p1, 2);
            p0 *= scale; p1 *= scale;
            mt0 = fmaxf(mt0, p0); mt1 = fmaxf(mt1, p1);
            if (g == 0) { Ss[c][r] = p0; Ss[c][r + 32] = p1; }
        }

        const float c0 = __expf(mo0 - mt0);
        const float c1 = __expf(mo1 - mt1);
        l0 *= c0; l1 *= c1;
#pragma unroll
        for (int j = 0; j < 32; j++) { a0[j] *= c0; a1[j] *= c1; }
        mo0 = mt0; mo1 = mt1;

        __syncthreads();
#pragma unroll
        for (int i = tid; i < 2048; i += 128) {
            const int rr = i >> 5, c = i & 31;
            *(float4*)(&KV[rr][c*4]) = *(const float4*)(Vb + (size_t)(n0 + rr) * DH_ + c*4);
        }
        __syncthreads();

#pragma unroll 2
        for (int c = 0; c < 64; c++) {
            const float p0 = __expf(Ss[c][r]      - mo0);
            const float p1 = __expf(Ss[c][r + 32] - mo1);
            l0 += p0; l1 += p1;
#pragma unroll
            for (int jj = 0; jj < 8; jj++) {
                const float4 v = *(const float4*)(&KV[c][jj*16 + g*4]);
                a0[jj*4+0] += p0*v.x; a0[jj*4+1] += p0*v.y;
                a0[jj*4+2] += p0*v.z; a0[jj*4+3] += p0*v.w;
                a1[jj*4+0] += p1*v.x; a1[jj*4+1] += p1*v.y;
                a1[jj*4+2] += p1*v.z; a1[jj*4+3] += p1*v.w;
            }
        }
    }

    const float i0 = 1.f / l0, i1 = 1.f / l1;
    const int bb = bh >> 4, h = bh & 15;
    float* o0 = ctx + ((size_t)bb * S_ + m0 + r)      * D_ + h * DH_;
    float* o1 = ctx + ((size_t)bb * S_ + m0 + r + 32) * D_ + h * DH_;
#pragma unroll
    for (int jj = 0; jj < 8; jj++) {
        float4 w0 = make_float4(a0[jj*4]*i0, a0[jj*4+1]*i0, a0[jj*4+2]*i0, a0[jj*4+3]*i0);
        float4 w1 = make_float4(a1[jj*4]*i1, a1[jj*4+1]*i1, a1[jj*4+2]*i1, a1[jj*4+3]*i1);
        *(float4*)(&o0[jj*16 + g*4]) = w0;
        *(float4*)(&o1[jj*16 + g*4]) = w1;
    }
}

// ---------------------------------------------------------------------------
extern "C" void kernel_launch(void* const* d_in, const int* in_sizes, int n_in,
                              void* d_out, int out_size)
{
    const float* x  = (const float*)d_in[0];
    const float* wq = (const float*)d_in[1];
    const float* bq = (const float*)d_in[2];
    const float* wk = (const float*)d_in[3];
    const float* bk = (const float*)d_in[4];
    const float* wv = (const float*)d_in[5];
    const float* bv = (const float*)d_in[6];
    const float* wo = (const float*)d_in[7];
    const float* bo = (const float*)d_in[8];
    float* out = (float*)d_out;

    float *q, *k, *v, *ctx;
    cudaGetSymbolAddress((void**)&q,   g_q);
    cudaGetSymbolAddress((void**)&k,   g_k);
    cudaGetSymbolAddress((void**)&v,   g_v);
    cudaGetSymbolAddress((void**)&ctx, g_ctx);

    const dim3 ggrid(D_ / 128, M_ / 128);   // (16, 64)

    rope_table_kernel<<<(S_ * 64) / 256, 256>>>();

    gemm_tf32<true><<<ggrid, 256>>>(x, wq, bq, q);
    gemm_tf32<true><<<ggrid, 256>>>(x, wk, bk, k);
    gemm_tf32<true><<<ggrid, 256>>>(x, wv, bv, v);

    const int rope_threads = B_ * H_ * S_ * 64;
    rope_apply_kernel<<<rope_threads / 256, 256>>>(q);
    rope_apply_kernel<<<rope_threads / 256, 256>>>(k);

    attn_kernel<<<dim3(S_ / 64, B_ * H_), 128>>>(ctx);

    gemm_tf32<false><<<ggrid, 256>>>(ctx, wo, bo, out);
}

// round 4
// speedup vs baseline: 3.5265x; 1.9410x over previous
#include <cuda_runtime.h>
#include <math.h>
#include <stdint.h>

#define B_  4
#define S_  2048
#define D_  2048
#define H_  16
#define DH_ 128
#define M_  (B_*S_)

// Scratch (allowed: __device__ globals)
__device__ float g_q[(size_t)B_*H_*S_*DH_];
__device__ float g_k[(size_t)B_*H_*S_*DH_];
__device__ float g_v[(size_t)B_*H_*S_*DH_];
__device__ float g_ctx[(size_t)B_*S_*D_];
__device__ float g_cos[(size_t)S_*64];
__device__ float g_sin[(size_t)S_*64];

// ---------------------------------------------------------------------------
// TF32 helpers
// ---------------------------------------------------------------------------
__device__ __forceinline__ uint32_t tf32u(float x) {
    uint32_t r;
    asm("cvt.rna.tf32.f32 %0, %1;" : "=r"(r) : "f"(x));
    return r;
}
__device__ __forceinline__ float f2tf32(float x) { return __uint_as_float(tf32u(x)); }

__device__ __forceinline__ void mma_tf32(float c[4], const uint32_t a[4], const uint32_t b[2]) {
    asm volatile(
        "mma.sync.aligned.m16n8k8.row.col.f32.tf32.tf32.f32 "
        "{%0,%1,%2,%3}, {%4,%5,%6,%7}, {%8,%9}, {%0,%1,%2,%3};"
        : "+f"(c[0]), "+f"(c[1]), "+f"(c[2]), "+f"(c[3])
        : "r"(a[0]), "r"(a[1]), "r"(a[2]), "r"(a[3]), "r"(b[0]), "r"(b[1]));
}

// ---------------------------------------------------------------------------
// TF32 tensor-core GEMM (unchanged from R2): C = A·Wᵀ + bias
// ---------------------------------------------------------------------------
template<bool HEADS>
__global__ __launch_bounds__(256)
void gemm_tf32(const float* __restrict__ A, const float* __restrict__ W,
               const float* __restrict__ bias, float* __restrict__ C)
{
    __shared__ float As[128][20];
    __shared__ float Ws[128][20];
    const int K  = D_;
    const int m0 = blockIdx.y * 128;
    const int n0 = blockIdx.x * 128;
    const int tid  = threadIdx.x;
    const int warp = tid >> 5, lane = tid & 31;
    const int wy = warp >> 2, wx = warp & 3;

    float acc[4][4][4];
#pragma unroll
    for (int ti = 0; ti < 4; ti++)
#pragma unroll
        for (int tj = 0; tj < 4; tj++)
#pragma unroll
            for (int e = 0; e < 4; e++) acc[ti][tj][e] = 0.f;

    const int lr = lane >> 2;
    const int lc = lane & 3;

    for (int k0 = 0; k0 < K; k0 += 16) {
#pragma unroll
        for (int u = 0; u < 2; u++) {
            const int f  = tid + u * 256;
            const int r  = f >> 2, c4 = f & 3;
            float4 av = *(const float4*)(A + (size_t)(m0 + r) * K + k0 + c4 * 4);
            av.x = f2tf32(av.x); av.y = f2tf32(av.y);
            av.z = f2tf32(av.z); av.w = f2tf32(av.w);
            *(float4*)(&As[r][c4 * 4]) = av;
            float4 wv = *(const float4*)(W + (size_t)(n0 + r) * K + k0 + c4 * 4);
            wv.x = f2tf32(wv.x); wv.y = f2tf32(wv.y);
            wv.z = f2tf32(wv.z); wv.w = f2tf32(wv.w);
            *(float4*)(&Ws[r][c4 * 4]) = wv;
        }
        __syncthreads();

#pragma unroll
        for (int kk = 0; kk < 16; kk += 8) {
            uint32_t afr[4][4], bfr[4][2];
            const int ac = kk + lc;
#pragma unroll
            for (int ti = 0; ti < 4; ti++) {
                const int ar = wy * 64 + ti * 16 + lr;
                afr[ti][0] = __float_as_uint(As[ar    ][ac]);
                afr[ti][1] = __float_as_uint(As[ar + 8][ac]);
                afr[ti][2] = __float_as_uint(As[ar    ][ac + 4]);
                afr[ti][3] = __float_as_uint(As[ar + 8][ac + 4]);
            }
#pragma unroll
            for (int tj = 0; tj < 4; tj++) {
                const int br = wx * 32 + tj * 8 + lr;
                bfr[tj][0] = __float_as_uint(Ws[br][ac]);
                bfr[tj][1] = __float_as_uint(Ws[br][ac + 4]);
            }
#pragma unroll
            for (int ti = 0; ti < 4; ti++)
#pragma unroll
                for (int tj = 0; tj < 4; tj++)
                    mma_tf32(acc[ti][tj], afr[ti], bfr[tj]);
        }
        __syncthreads();
    }

#pragma unroll
    for (int ti = 0; ti < 4; ti++) {
#pragma unroll
        for (int tj = 0; tj < 4; tj++) {
            const int row = m0 + wy * 64 + ti * 16 + lr;
            const int col = n0 + wx * 32 + tj * 8 + lc * 2;
#pragma unroll
            for (int e = 0; e < 4; e++) {
                const int m = row + (e >> 1) * 8;
                const int n = col + (e & 1);
                const float v = acc[ti][tj][e] + bias[n];
                if (HEADS) {
                    const int bb = m >> 11, s = m & (S_ - 1);
                    const int h = n >> 7, dh = n & 127;
                    C[(((size_t)bb * H_ + h) * S_ + s) * DH_ + dh] = v;
                } else {
                    C[(size_t)m * D_ + n] = v;
                }
            }
        }
    }
}

// ---------------------------------------------------------------------------
// RoPE table + streaming apply
// ---------------------------------------------------------------------------
__global__ __launch_bounds__(256)
void rope_table_kernel()
{
    const int idx = blockIdx.x * blockDim.x + threadIdx.x;
    const int p = idx & 63;
    const int s = idx >> 6;
    const float invf = (float)exp(-(double)p * (log(10000.0) / 64.0));
    const float ang  = (float)s * invf;
    g_cos[idx] = (float)cos((double)ang);
    g_sin[idx] = (float)sin((double)ang);
}

__global__ __launch_bounds__(256)
void rope_apply_kernel(float* __restrict__ t)
{
    const int idx = blockIdx.x * blockDim.x + threadIdx.x;
    const int p   = idx & 63;
    const int row = idx >> 6;
    const int s   = row & (S_ - 1);

    const float cs = g_cos[s * 64 + p];
    const float sn = g_sin[s * 64 + p];

    float* base = t + (size_t)row * DH_;
    const float v1 = base[p];
    const float v2 = base[p + 64];
    base[p]      = v1 * cs - v2 * sn;
    base[p + 64] = v2 * cs + v1 * sn;
}

// ---------------------------------------------------------------------------
// TF32 tensor-core flash attention, non-causal.
// Grid (S/64, B*H), 128 threads (4 warps). Warp w owns q-rows w*16..w*16+15.
// Q frags resident in registers (scaled, tf32). Per 64-key tile:
//   S = Q·Kᵀ (mma, K key-major in smem) → online softmax in accumulator
//   layout (shfl row-reductions) → P to smem (tf32) → O += P·V (mma,
//   V transposed to Vt[d][key] at load).
// Smem strides 132/68/76 make all fragment LDS bank-conflict-free.
// ---------------------------------------------------------------------------
#define KPAD 132
#define VPAD 68
#define PPAD 76
#define SMEM_ATTN ((64*KPAD + 128*VPAD + 64*PPAD) * 4)

__global__ __launch_bounds__(128)
void attn_mma(float* __restrict__ ctx)
{
    extern __shared__ float sm[];
    float* Ks = sm;                          // [64][KPAD]  K tile (also Q staging)
    float* Vt = sm + 64 * KPAD;              // [128][VPAD] V transposed
    float* Ps = sm + 64 * KPAD + 128 * VPAD; // [64][PPAD]  P scores

    const int bh  = blockIdx.y;
    const int m0  = blockIdx.x * 64;
    const int tid = threadIdx.x;
    const int warp = tid >> 5, lane = tid & 31;
    const int lr = lane >> 2, lc = lane & 3;
    const int qr = warp * 16;

    const float* Qb = g_q + (size_t)bh * S_ * DH_;
    const float* Kb = g_k + (size_t)bh * S_ * DH_;
    const float* Vb = g_v + (size_t)bh * S_ * DH_;

    // ---- stage scaled Q (tf32) into Ks, then lift to register fragments ----
    const float scale = 0.08838834764831845f;  // 1/sqrt(128)
#pragma unroll
    for (int i = 0; i < 16; i++) {
        const int idx = tid + i * 128;
        const int r = idx >> 5, c4 = idx & 31;
        float4 v = *(const float4*)(Qb + (size_t)(m0 + r) * DH_ + c4 * 4);
        v.x = f2tf32(v.x * scale); v.y = f2tf32(v.y * scale);
        v.z = f2tf32(v.z * scale); v.w = f2tf32(v.w * scale);
        *(float4*)(&Ks[r * KPAD + c4 * 4]) = v;
    }
    __syncthreads();
    uint32_t qf[16][4];
#pragma unroll
    for (int ks = 0; ks < 16; ks++) {
        qf[ks][0] = __float_as_uint(Ks[(qr + lr    ) * KPAD + ks * 8 + lc    ]);
        qf[ks][1] = __float_as_uint(Ks[(qr + lr + 8) * KPAD + ks * 8 + lc    ]);
        qf[ks][2] = __float_as_uint(Ks[(qr + lr    ) * KPAD + ks * 8 + lc + 4]);
        qf[ks][3] = __float_as_uint(Ks[(qr + lr + 8) * KPAD + ks * 8 + lc + 4]);
    }

    float oacc[16][4];
#pragma unroll
    for (int nt = 0; nt < 16; nt++)
#pragma unroll
        for (int e = 0; e < 4; e++) oacc[nt][e] = 0.f;
    float mr0 = -1e30f, mr1 = -1e30f, lsum0 = 0.f, lsum1 = 0.f;

    for (int kt = 0; kt < 32; kt++) {
        __syncthreads();  // prev tile fully consumed (also guards Q staging)
        const int key0 = kt * 64;
        // K tile: key-major, tf32
#pragma unroll
        for (int i = 0; i < 16; i++) {
            const int idx = tid + i * 128;
            const int r = idx >> 5, c4 = idx & 31;
            float4 v = *(const float4*)(Kb + (size_t)(key0 + r) * DH_ + c4 * 4);
            v.x = f2tf32(v.x); v.y = f2tf32(v.y);
            v.z = f2tf32(v.z); v.w = f2tf32(v.w);
            *(float4*)(&Ks[r * KPAD + c4 * 4]) = v;
        }
        // V tile transposed: Vt[d][key], tf32. Per warp: 32 consecutive keys,
        // one d4 chunk -> conflict-free STS.
#pragma unroll
        for (int i = 0; i < 16; i++) {
            const int idx = tid + i * 128;
            const int d4 = idx >> 6, key = idx & 63;
            float4 v = *(const float4*)(Vb + (size_t)(key0 + key) * DH_ + d4 * 4);
            Vt[(d4 * 4 + 0) * VPAD + key] = f2tf32(v.x);
            Vt[(d4 * 4 + 1) * VPAD + key] = f2tf32(v.y);
            Vt[(d4 * 4 + 2) * VPAD + key] = f2tf32(v.z);
            Vt[(d4 * 4 + 3) * VPAD + key] = f2tf32(v.w);
        }
        __syncthreads();

        // ---- S = Q·Kᵀ (scaled) ----
        float sacc[8][4];
#pragma unroll
        for (int n = 0; n < 8; n++)
#pragma unroll
            for (int e = 0; e < 4; e++) sacc[n][e] = 0.f;
#pragma unroll
        for (int ks = 0; ks < 16; ks++) {
#pragma unroll
            for (int n = 0; n < 8; n++) {
                uint32_t b[2];
                b[0] = __float_as_uint(Ks[(n * 8 + lr) * KPAD + ks * 8 + lc    ]);
                b[1] = __float_as_uint(Ks[(n * 8 + lr) * KPAD + ks * 8 + lc + 4]);
                mma_tf32(sacc[n], qf[ks], b);
            }
        }

        // ---- online softmax ----
        float mx0 = mr0, mx1 = mr1;
#pragma unroll
        for (int n = 0; n < 8; n++) {
            mx0 = fmaxf(mx0, fmaxf(sacc[n][0], sacc[n][1]));
            mx1 = fmaxf(mx1, fmaxf(sacc[n][2], sacc[n][3]));
        }
        mx0 = fmaxf(mx0, __shfl_xor_sync(0xffffffffu, mx0, 1));
        mx0 = fmaxf(mx0, __shfl_xor_sync(0xffffffffu, mx0, 2));
        mx1 = fmaxf(mx1, __shfl_xor_sync(0xffffffffu, mx1, 1));
        mx1 = fmaxf(mx1, __shfl_xor_sync(0xffffffffu, mx1, 2));
        const float f0 = __expf(mr0 - mx0);
        const float f1 = __expf(mr1 - mx1);
        mr0 = mx0; mr1 = mx1;

        float s0 = 0.f, s1 = 0.f;
#pragma unroll
        for (int n = 0; n < 8; n++) {
            const float p0 = __expf(sacc[n][0] - mx0);
            const float p1 = __expf(sacc[n][1] - mx0);
            const float p2 = __expf(sacc[n][2] - mx1);
            const float p3 = __expf(sacc[n][3] - mx1);
            s0 += p0 + p1; s1 += p2 + p3;
            float2 lo; lo.x = f2tf32(p0); lo.y = f2tf32(p1);
            *(float2*)(&Ps[(qr + lr    ) * PPAD + n * 8 + lc * 2]) = lo;
            float2 hi; hi.x = f2tf32(p2); hi.y = f2tf32(p3);
            *(float2*)(&Ps[(qr + lr + 8) * PPAD + n * 8 + lc * 2]) = hi;
        }
        s0 += __shfl_xor_sync(0xffffffffu, s0, 1);
        s0 += __shfl_xor_sync(0xffffffffu, s0, 2);
        s1 += __shfl_xor_sync(0xffffffffu, s1, 1);
        s1 += __shfl_xor_sync(0xffffffffu, s1, 2);
        lsum0 = lsum0 * f0 + s0;
        lsum1 = lsum1 * f1 + s1;
#pragma unroll
        for (int nt = 0; nt < 16; nt++) {
            oacc[nt][0] *= f0; oacc[nt][1] *= f0;
            oacc[nt][2] *= f1; oacc[nt][3] *= f1;
        }
        __syncwarp();  // order own-warp P stores before P fragment loads

        // ---- O += P·V ----
#pragma unroll
        for (int kk = 0; kk < 8; kk++) {
            uint32_t af[4];
            af[0] = __float_as_uint(Ps[(qr + lr    ) * PPAD + kk * 8 + lc    ]);
            af[1] = __float_as_uint(Ps[(qr + lr + 8) * PPAD + kk * 8 + lc    ]);
            af[2] = __float_as_uint(Ps[(qr + lr    ) * PPAD + kk * 8 + lc + 4]);
            af[3] = __float_as_uint(Ps[(qr + lr + 8) * PPAD + kk * 8 + lc + 4]);
#pragma unroll
            for (int nt = 0; nt < 16; nt++) {
                uint32_t b[2];
                b[0] = __float_as_uint(Vt[(nt * 8 + lr) * VPAD + kk * 8 + lc    ]);
                b[1] = __float_as_uint(Vt[(nt * 8 + lr) * VPAD + kk * 8 + lc + 4]);
                mma_tf32(oacc[nt], af, b);
            }
        }
    }

    // ---- epilogue: normalize + scatter to ctx[b][s][h*128+d] ----
    const float i0 = 1.f / lsum0, i1 = 1.f / lsum1;
    const int bb = bh >> 4, h = bh & 15;
    const int gr0 = m0 + qr + lr;
    float* o0 = ctx + ((size_t)bb * S_ + gr0) * D_ + h * DH_;
    float* o1 = o0 + (size_t)8 * D_;
#pragma unroll
    for (int nt = 0; nt < 16; nt++) {
        float2 a; a.x = oacc[nt][0] * i0; a.y = oacc[nt][1] * i0;
        *(float2*)(o0 + nt * 8 + lc * 2) = a;
        float2 b; b.x = oacc[nt][2] * i1; b.y = oacc[nt][3] * i1;
        *(float2*)(o1 + nt * 8 + lc * 2) = b;
    }
}

// ---------------------------------------------------------------------------
extern "C" void kernel_launch(void* const* d_in, const int* in_sizes, int n_in,
                              void* d_out, int out_size)
{
    const float* x  = (const float*)d_in[0];
    const float* wq = (const float*)d_in[1];
    const float* bq = (const float*)d_in[2];
    const float* wk = (const float*)d_in[3];
    const float* bk = (const float*)d_in[4];
    const float* wv = (const float*)d_in[5];
    const float* bv = (const float*)d_in[6];
    const float* wo = (const float*)d_in[7];
    const float* bo = (const float*)d_in[8];
    float* out = (float*)d_out;

    float *q, *k, *v, *ctx;
    cudaGetSymbolAddress((void**)&q,   g_q);
    cudaGetSymbolAddress((void**)&k,   g_k);
    cudaGetSymbolAddress((void**)&v,   g_v);
    cudaGetSymbolAddress((void**)&ctx, g_ctx);

    cudaFuncSetAttribute(attn_mma, cudaFuncAttributeMaxDynamicSharedMemorySize, SMEM_ATTN);

    const dim3 ggrid(D_ / 128, M_ / 128);   // (16, 64)

    rope_table_kernel<<<(S_ * 64) / 256, 256>>>();

    gemm_tf32<true><<<ggrid, 256>>>(x, wq, bq, q);
    gemm_tf32<true><<<ggrid, 256>>>(x, wk, bk, k);
    gemm_tf32<true><<<ggrid, 256>>>(x, wv, bv, v);

    const int rope_threads = B_ * H_ * S_ * 64;
    rope_apply_kernel<<<rope_threads / 256, 256>>>(q);
    rope_apply_kernel<<<rope_threads / 256, 256>>>(k);

    attn_mma<<<dim3(S_ / 64, B_ * H_), 128, SMEM_ATTN>>>(ctx);

    gemm_tf32<false><<<ggrid, 256>>>(ctx, wo, bo, out);
}

// round 6
// speedup vs baseline: 3.7111x; 1.0524x over previous
#include <cuda_runtime.h>
#include <math.h>
#include <stdint.h>

#define B_  4
#define S_  2048
#define D_  2048
#define H_  16
#define DH_ 128
#define M_  (B_*S_)

// Scratch (allowed: __device__ globals)
__device__ float g_q[(size_t)B_*H_*S_*DH_];
__device__ float g_k[(size_t)B_*H_*S_*DH_];
__device__ float g_v[(size_t)B_*H_*S_*DH_];
__device__ float g_ctx[(size_t)B_*S_*D_];
__device__ float g_cos[(size_t)S_*64];
__device__ float g_sin[(size_t)S_*64];

// ---------------------------------------------------------------------------
// TF32 helpers
// ---------------------------------------------------------------------------
__device__ __forceinline__ uint32_t tf32u(float x) {
    uint32_t r;
    asm("cvt.rna.tf32.f32 %0, %1;" : "=r"(r) : "f"(x));
    return r;
}
__device__ __forceinline__ float f2tf32(float x) { return __uint_as_float(tf32u(x)); }

__device__ __forceinline__ void mma_tf32(float c[4], const uint32_t a[4], const uint32_t b[2]) {
    asm volatile(
        "mma.sync.aligned.m16n8k8.row.col.f32.tf32.tf32.f32 "
        "{%0,%1,%2,%3}, {%4,%5,%6,%7}, {%8,%9}, {%0,%1,%2,%3};"
        : "+f"(c[0]), "+f"(c[1]), "+f"(c[2]), "+f"(c[3])
        : "r"(a[0]), "r"(a[1]), "r"(a[2]), "r"(a[3]), "r"(b[0]), "r"(b[1]));
}

// ---------------------------------------------------------------------------
// TF32 tensor-core GEMM: C[m][n] = sum_k A[m][k]*W[n][k] + bias[n]
// 128x128 block, 128 threads (4 warps, 2x2 grid), 64x64 warp tile.
// Double-buffered smem with register prefetch: one __syncthreads per k16.
// Stride-20 smem rows -> all fragment LDS conflict-free.
// ---------------------------------------------------------------------------
template<bool HEADS>
__global__ __launch_bounds__(128)
void gemm_tf32(const float* __restrict__ A, const float* __restrict__ W,
               const float* __restrict__ bias, float* __restrict__ C)
{
    __shared__ float As[2][128][20];
    __shared__ float Ws[2][128][20];
    const int K  = D_;
    const int m0 = blockIdx.y * 128;
    const int n0 = blockIdx.x * 128;
    const int tid  = threadIdx.x;
    const int warp = tid >> 5, lane = tid & 31;
    const int wy = warp >> 1, wx = warp & 1;     // 2x2 warp grid
    const int lr = lane >> 2, lc = lane & 3;

    float acc[4][8][4];
#pragma unroll
    for (int ti = 0; ti < 4; ti++)
#pragma unroll
        for (int nt = 0; nt < 8; nt++)
#pragma unroll
            for (int e = 0; e < 4; e++) acc[ti][nt][e] = 0.f;

    // prologue: load k-tile 0 straight into buffer 0
    float4 pa[4], pw[4];
#pragma unroll
    for (int u = 0; u < 4; u++) {
        const int f = tid + u * 128;            // float4 idx 0..511
        const int r = f >> 2, c4 = f & 3;
        pa[u] = *(const float4*)(A + (size_t)(m0 + r) * K + c4 * 4);
        pw[u] = *(const float4*)(W + (size_t)(n0 + r) * K + c4 * 4);
    }
#pragma unroll
    for (int u = 0; u < 4; u++) {
        const int f = tid + u * 128;
        const int r = f >> 2, c4 = f & 3;
        float4 av = pa[u];
        av.x = f2tf32(av.x); av.y = f2tf32(av.y);
        av.z = f2tf32(av.z); av.w = f2tf32(av.w);
        *(float4*)(&As[0][r][c4 * 4]) = av;
        float4 wv = pw[u];
        wv.x = f2tf32(wv.x); wv.y = f2tf32(wv.y);
        wv.z = f2tf32(wv.z); wv.w = f2tf32(wv.w);
        *(float4*)(&Ws[0][r][c4 * 4]) = wv;
    }

    const int NIT = K / 16;                     // 128
    for (int it = 0; it < NIT; it++) {
        __syncthreads();
        const int cur = it & 1;
        const bool more = (it + 1 < NIT);
        if (more) {
            const int k0 = (it + 1) * 16;
#pragma unroll
            for (int u = 0; u < 4; u++) {
                const int f = tid + u * 128;
                const int r = f >> 2, c4 = f & 3;
                pa[u] = *(const float4*)(A + (size_t)(m0 + r) * K + k0 + c4 * 4);
                pw[u] = *(const float4*)(W + (size_t)(n0 + r) * K + k0 + c4 * 4);
            }
        }

#pragma unroll
        for (int kk = 0; kk < 16; kk += 8) {
            uint32_t afr[4][4], bfr[8][2];
            const int ac = kk + lc;
#pragma unroll
            for (int ti = 0; ti < 4; ti++) {
                const int ar = wy * 64 + ti * 16 + lr;
                afr[ti][0] = __float_as_uint(As[cur][ar    ][ac]);
                afr[ti][1] = __float_as_uint(As[cur][ar + 8][ac]);
                afr[ti][2] = __float_as_uint(As[cur][ar    ][ac + 4]);
                afr[ti][3] = __float_as_uint(As[cur][ar + 8][ac + 4]);
            }
#pragma unroll
            for (int nt = 0; nt < 8; nt++) {
                const int br = wx * 64 + nt * 8 + lr;
                bfr[nt][0] = __float_as_uint(Ws[cur][br][ac]);
                bfr[nt][1] = __float_as_uint(Ws[cur][br][ac + 4]);
            }
#pragma unroll
            for (int ti = 0; ti < 4; ti++)
#pragma unroll
                for (int nt = 0; nt < 8; nt++)
                    mma_tf32(acc[ti][nt], afr[ti], bfr[nt]);
        }

        if (more) {
            const int nxt = cur ^ 1;
#pragma unroll
            for (int u = 0; u < 4; u++) {
                const int f = tid + u * 128;
                const int r = f >> 2, c4 = f & 3;
                float4 av = pa[u];
                av.x = f2tf32(av.x); av.y = f2tf32(av.y);
                av.z = f2tf32(av.z); av.w = f2tf32(av.w);
                *(float4*)(&As[nxt][r][c4 * 4]) = av;
                float4 wv = pw[u];
                wv.x = f2tf32(wv.x); wv.y = f2tf32(wv.y);
                wv.z = f2tf32(wv.z); wv.w = f2tf32(wv.w);
                *(float4*)(&Ws[nxt][r][c4 * 4]) = wv;
            }
        }
    }

    // epilogue
#pragma unroll
    for (int ti = 0; ti < 4; ti++) {
#pragma unroll
        for (int nt = 0; nt < 8; nt++) {
            const int row = m0 + wy * 64 + ti * 16 + lr;
            const int col = n0 + wx * 64 + nt * 8 + lc * 2;
#pragma unroll
            for (int e = 0; e < 4; e++) {
                const int m = row + (e >> 1) * 8;
                const int n = col + (e & 1);
                const float v = acc[ti][nt][e] + bias[n];
                if (HEADS) {
                    const int bb = m >> 11, s = m & (S_ - 1);
                    const int h = n >> 7, dh = n & 127;
                    C[(((size_t)bb * H_ + h) * S_ + s) * DH_ + dh] = v;
                } else {
                    C[(size_t)m * D_ + n] = v;
                }
            }
        }
    }
}

// ---------------------------------------------------------------------------
// RoPE table + streaming apply
// ---------------------------------------------------------------------------
__global__ __launch_bounds__(256)
void rope_table_kernel()
{
    const int idx = blockIdx.x * blockDim.x + threadIdx.x;
    const int p = idx & 63;
    const int s = idx >> 6;
    const float invf = (float)exp(-(double)p * (log(10000.0) / 64.0));
    const float ang  = (float)s * invf;
    g_cos[idx] = (float)cos((double)ang);
    g_sin[idx] = (float)sin((double)ang);
}

__global__ __launch_bounds__(256)
void rope_apply_kernel(float* __restrict__ t)
{
    const int idx = blockIdx.x * blockDim.x + threadIdx.x;
    const int p   = idx & 63;
    const int row = idx >> 6;
    const int s   = row & (S_ - 1);

    const float cs = g_cos[s * 64 + p];
    const float sn = g_sin[s * 64 + p];

    float* base = t + (size_t)row * DH_;
    const float v1 = base[p];
    const float v2 = base[p + 64];
    base[p]      = v1 * cs - v2 * sn;
    base[p + 64] = v2 * cs + v1 * sn;
}

// ---------------------------------------------------------------------------
// TF32 tensor-core flash attention (unchanged from R3).
// ---------------------------------------------------------------------------
#define KPAD 132
#define VPAD 68
#define PPAD 76
#define SMEM_ATTN ((64*KPAD + 128*VPAD + 64*PPAD) * 4)

__global__ __launch_bounds__(128)
void attn_mma(float* __restrict__ ctx)
{
    extern __shared__ float sm[];
    float* Ks = sm;
    float* Vt = sm + 64 * KPAD;
    float* Ps = sm + 64 * KPAD + 128 * VPAD;

    const int bh  = blockIdx.y;
    const int m0  = blockIdx.x * 64;
    const int tid = threadIdx.x;
    const int warp = tid >> 5, lane = tid & 31;
    const int lr = lane >> 2, lc = lane & 3;
    const int qr = warp * 16;

    const float* Qb = g_q + (size_t)bh * S_ * DH_;
    const float* Kb = g_k + (size_t)bh * S_ * DH_;
    const float* Vb = g_v + (size_t)bh * S_ * DH_;

    const float scale = 0.08838834764831845f;
#pragma unroll
    for (int i = 0; i < 16; i++) {
        const int idx = tid + i * 128;
        const int r = idx >> 5, c4 = idx & 31;
        float4 v = *(const float4*)(Qb + (size_t)(m0 + r) * DH_ + c4 * 4);
        v.x = f2tf32(v.x * scale); v.y = f2tf32(v.y * scale);
        v.z = f2tf32(v.z * scale); v.w = f2tf32(v.w * scale);
        *(float4*)(&Ks[r * KPAD + c4 * 4]) = v;
    }
    __syncthreads();
    uint32_t qf[16][4];
#pragma unroll
    for (int ks = 0; ks < 16; ks++) {
        qf[ks][0] = __float_as_uint(Ks[(qr + lr    ) * KPAD + ks * 8 + lc    ]);
        qf[ks][1] = __float_as_uint(Ks[(qr + lr + 8) * KPAD + ks * 8 + lc    ]);
        qf[ks][2] = __float_as_uint(Ks[(qr + lr    ) * KPAD + ks * 8 + lc + 4]);
        qf[ks][3] = __float_as_uint(Ks[(qr + lr + 8) * KPAD + ks * 8 + lc + 4]);
    }

    float oacc[16][4];
#pragma unroll
    for (int nt = 0; nt < 16; nt++)
#pragma unroll
        for (int e = 0; e < 4; e++) oacc[nt][e] = 0.f;
    float mr0 = -1e30f, mr1 = -1e30f, lsum0 = 0.f, lsum1 = 0.f;

    for (int kt = 0; kt < 32; kt++) {
        __syncthreads();
        const int key0 = kt * 64;
#pragma unroll
        for (int i = 0; i < 16; i++) {
            const int idx = tid + i * 128;
            const int r = idx >> 5, c4 = idx & 31;
            float4 v = *(const float4*)(Kb + (size_t)(key0 + r) * DH_ + c4 * 4);
            v.x = f2tf32(v.x); v.y = f2tf32(v.y);
            v.z = f2tf32(v.z); v.w = f2tf32(v.w);
            *(float4*)(&Ks[r * KPAD + c4 * 4]) = v;
        }
#pragma unroll
        for (int i = 0; i < 16; i++) {
            const int idx = tid + i * 128;
            const int d4 = idx >> 6, key = idx & 63;
            float4 v = *(const float4*)(Vb + (size_t)(key0 + key) * DH_ + d4 * 4);
            Vt[(d4 * 4 + 0) * VPAD + key] = f2tf32(v.x);
            Vt[(d4 * 4 + 1) * VPAD + key] = f2tf32(v.y);
            Vt[(d4 * 4 + 2) * VPAD + key] = f2tf32(v.z);
            Vt[(d4 * 4 + 3) * VPAD + key] = f2tf32(v.w);
        }
        __syncthreads();

        float sacc[8][4];
#pragma unroll
        for (int n = 0; n < 8; n++)
#pragma unroll
            for (int e = 0; e < 4; e++) sacc[n][e] = 0.f;
#pragma unroll
        for (int ks = 0; ks < 16; ks++) {
#pragma unroll
            for (int n = 0; n < 8; n++) {
                uint32_t b[2];
                b[0] = __float_as_uint(Ks[(n * 8 + lr) * KPAD + ks * 8 + lc    ]);
                b[1] = __float_as_uint(Ks[(n * 8 + lr) * KPAD + ks * 8 + lc + 4]);
                mma_tf32(sacc[n], qf[ks], b);
            }
        }

        float mx0 = mr0, mx1 = mr1;
#pragma unroll
        for (int n = 0; n < 8; n++) {
            mx0 = fmaxf(mx0, fmaxf(sacc[n][0], sacc[n][1]));
            mx1 = fmaxf(mx1, fmaxf(sacc[n][2], sacc[n][3]));
        }
        mx0 = fmaxf(mx0, __shfl_xor_sync(0xffffffffu, mx0, 1));
        mx0 = fmaxf(mx0, __shfl_xor_sync(0xffffffffu, mx0, 2));
        mx1 = fmaxf(mx1, __shfl_xor_sync(0xffffffffu, mx1, 1));
        mx1 = fmaxf(mx1, __shfl_xor_sync(0xffffffffu, mx1, 2));
        const float f0 = __expf(mr0 - mx0);
        const float f1 = __expf(mr1 - mx1);
        mr0 = mx0; mr1 = mx1;

        float s0 = 0.f, s1 = 0.f;
#pragma unroll
        for (int n = 0; n < 8; n++) {
            const float p0 = __expf(sacc[n][0] - mx0);
            const float p1 = __expf(sacc[n][1] - mx0);
            const float p2 = __expf(sacc[n][2] - mx1);
            const float p3 = __expf(sacc[n][3] - mx1);
            s0 += p0 + p1; s1 += p2 + p3;
            float2 lo; lo.x = f2tf32(p0); lo.y = f2tf32(p1);
            *(float2*)(&Ps[(qr + lr    ) * PPAD + n * 8 + lc * 2]) = lo;
            float2 hi; hi.x = f2tf32(p2); hi.y = f2tf32(p3);
            *(float2*)(&Ps[(qr + lr + 8) * PPAD + n * 8 + lc * 2]) = hi;
        }
        s0 += __shfl_xor_sync(0xffffffffu, s0, 1);
        s0 += __shfl_xor_sync(0xffffffffu, s0, 2);
        s1 += __shfl_xor_sync(0xffffffffu, s1, 1);
        s1 += __shfl_xor_sync(0xffffffffu, s1, 2);
        lsum0 = lsum0 * f0 + s0;
        lsum1 = lsum1 * f1 + s1;
#pragma unroll
        for (int nt = 0; nt < 16; nt++) {
            oacc[nt][0] *= f0; oacc[nt][1] *= f0;
            oacc[nt][2] *= f1; oacc[nt][3] *= f1;
        }
        __syncwarp();

#pragma unroll
        for (int kk = 0; kk < 8; kk++) {
            uint32_t af[4];
            af[0] = __float_as_uint(Ps[(qr + lr    ) * PPAD + kk * 8 + lc    ]);
            af[1] = __float_as_uint(Ps[(qr + lr + 8) * PPAD + kk * 8 + lc    ]);
            af[2] = __float_as_uint(Ps[(qr + lr    ) * PPAD + kk * 8 + lc + 4]);
            af[3] = __float_as_uint(Ps[(qr + lr + 8) * PPAD + kk * 8 + lc + 4]);
#pragma unroll
            for (int nt = 0; nt < 16; nt++) {
                uint32_t b[2];
                b[0] = __float_as_uint(Vt[(nt * 8 + lr) * VPAD + kk * 8 + lc    ]);
                b[1] = __float_as_uint(Vt[(nt * 8 + lr) * VPAD + kk * 8 + lc + 4]);
                mma_tf32(oacc[nt], af, b);
            }
        }
    }

    const float i0 = 1.f / lsum0, i1 = 1.f / lsum1;
    const int bb = bh >> 4, h = bh & 15;
    const int gr0 = m0 + qr + lr;
    float* o0 = ctx + ((size_t)bb * S_ + gr0) * D_ + h * DH_;
    float* o1 = o0 + (size_t)8 * D_;
#pragma unroll
    for (int nt = 0; nt < 16; nt++) {
        float2 a; a.x = oacc[nt][0] * i0; a.y = oacc[nt][1] * i0;
        *(float2*)(o0 + nt * 8 + lc * 2) = a;
        float2 b; b.x = oacc[nt][2] * i1; b.y = oacc[nt][3] * i1;
        *(float2*)(o1 + nt * 8 + lc * 2) = b;
    }
}

// ---------------------------------------------------------------------------
extern "C" void kernel_launch(void* const* d_in, const int* in_sizes, int n_in,
                              void* d_out, int out_size)
{
    const float* x  = (const float*)d_in[0];
    const float* wq = (const float*)d_in[1];
    const float* bq = (const float*)d_in[2];
    const float* wk = (const float*)d_in[3];
    const float* bk = (const float*)d_in[4];
    const float* wv = (const float*)d_in[5];
    const float* bv = (const float*)d_in[6];
    const float* wo = (const float*)d_in[7];
    const float* bo = (const float*)d_in[8];
    float* out = (float*)d_out;

    float *q, *k, *v, *ctx;
    cudaGetSymbolAddress((void**)&q,   g_q);
    cudaGetSymbolAddress((void**)&k,   g_k);
    cudaGetSymbolAddress((void**)&v,   g_v);
    cudaGetSymbolAddress((void**)&ctx, g_ctx);

    cudaFuncSetAttribute(attn_mma, cudaFuncAttributeMaxDynamicSharedMemorySize, SMEM_ATTN);

    const dim3 ggrid(D_ / 128, M_ / 128);   // (16, 64)

    rope_table_kernel<<<(S_ * 64) / 256, 256>>>();

    gemm_tf32<true><<<ggrid, 128>>>(x, wq, bq, q);
    gemm_tf32<true><<<ggrid, 128>>>(x, wk, bk, k);
    gemm_tf32<true><<<ggrid, 128>>>(x, wv, bv, v);

    const int rope_threads = B_ * H_ * S_ * 64;
    rope_apply_kernel<<<rope_threads / 256, 256>>>(q);
    rope_apply_kernel<<<rope_threads / 256, 256>>>(k);

    attn_mma<<<dim3(S_ / 64, B_ * H_), 128, SMEM_ATTN>>>(ctx);

    gemm_tf32<false><<<ggrid, 128>>>(ctx, wo, bo, out);
}